// round 2
// baseline (speedup 1.0000x reference)
#include <cuda_runtime.h>
#include <cstdint>

#define N_TOKENS 8192
#define IN_F     4096
#define OUT_F    16384

#define BM 128
#define BN 128
#define BK 64              // int8 elems per k-chunk
#define NKC (IN_F / BK)    // 64
#define NSTAGE 4
#define THREADS 512

// smem stage layout: rows padded 64B -> 80B (conflict-free 4B fragment reads)
#define ROW_PITCH 80
#define B_OFF   0
#define AH_OFF  (128 * ROW_PITCH)          // 10240
#define AL_OFF  (2 * 128 * ROW_PITCH)      // 20480
#define STAGE_BYTES (3 * 128 * ROW_PITCH)  // 30720
#define SMEM_BYTES  (NSTAGE * STAGE_BYTES) // 122880

// quantization constants: x ~= S0*q_hi + S1*q_lo
#define S0 0.0625f
#define S1 (0.0625f / 252.0f)

// -------- static scratch (no runtime allocation allowed) --------
__device__ int8_t g_W8 [(size_t)OUT_F * IN_F];     // 64 MB
__device__ int8_t g_Xhi[(size_t)N_TOKENS * IN_F];  // 32 MB
__device__ int8_t g_Xlo[(size_t)N_TOKENS * IN_F];  // 32 MB

// ---------------- helpers ----------------
__device__ __forceinline__ uint32_t smem_u32(const void* p) {
    uint32_t a;
    asm("{ .reg .u64 t; cvta.to.shared.u64 t, %1; cvt.u32.u64 %0, t; }" : "=r"(a) : "l"(p));
    return a;
}

__device__ __forceinline__ void cp_async16(uint32_t dst, const void* src) {
    asm volatile("cp.async.cg.shared.global [%0], [%1], 16;" :: "r"(dst), "l"(src));
}

__device__ __forceinline__ int lds32(uint32_t a) {
    int v;
    asm volatile("ld.shared.b32 %0, [%1];" : "=r"(v) : "r"(a));
    return v;
}

__device__ __forceinline__ void mma_s8(int* c, int a0, int a1, int a2, int a3,
                                       int b0, int b1) {
    asm volatile(
        "mma.sync.aligned.m16n8k32.row.col.s32.s8.s8.s32 "
        "{%0,%1,%2,%3}, {%4,%5,%6,%7}, {%8,%9}, {%0,%1,%2,%3};"
        : "+r"(c[0]), "+r"(c[1]), "+r"(c[2]), "+r"(c[3])
        : "r"(a0), "r"(a1), "r"(a2), "r"(a3), "r"(b0), "r"(b1));
}

// ---------------- conversion kernels ----------------
__global__ void convert_w_kernel(const int* __restrict__ w) {
    size_t i = ((size_t)blockIdx.x * blockDim.x + threadIdx.x) * 16;
    const int4* p = (const int4*)(w + i);
    int4 a = p[0], b = p[1], c = p[2], d = p[3];
    uint4 st;
    st.x = (a.x & 255) | ((a.y & 255) << 8) | ((a.z & 255) << 16) | (a.w << 24);
    st.y = (b.x & 255) | ((b.y & 255) << 8) | ((b.z & 255) << 16) | (b.w << 24);
    st.z = (c.x & 255) | ((c.y & 255) << 8) | ((c.z & 255) << 16) | (c.w << 24);
    st.w = (d.x & 255) | ((d.y & 255) << 8) | ((d.z & 255) << 16) | (d.w << 24);
    *(uint4*)(g_W8 + i) = st;
}

__global__ void convert_x_kernel(const float* __restrict__ x) {
    size_t i = ((size_t)blockIdx.x * blockDim.x + threadIdx.x) * 8;
    float4 v0 = *(const float4*)(x + i);
    float4 v1 = *(const float4*)(x + i + 4);
    float vv[8] = {v0.x, v0.y, v0.z, v0.w, v1.x, v1.y, v1.z, v1.w};
    int qh[8], ql[8];
#pragma unroll
    for (int u = 0; u < 8; u++) {
        float h = rintf(vv[u] * 16.0f);              // x / S0
        h = fminf(fmaxf(h, -127.0f), 127.0f);
        float r = vv[u] - h * S0;
        float l = rintf(r * (16.0f * 252.0f));       // r / S1
        l = fminf(fmaxf(l, -127.0f), 127.0f);
        qh[u] = (int)h;
        ql[u] = (int)l;
    }
    uint2 sh, sl;
    sh.x = (qh[0] & 255) | ((qh[1] & 255) << 8) | ((qh[2] & 255) << 16) | (qh[3] << 24);
    sh.y = (qh[4] & 255) | ((qh[5] & 255) << 8) | ((qh[6] & 255) << 16) | (qh[7] << 24);
    sl.x = (ql[0] & 255) | ((ql[1] & 255) << 8) | ((ql[2] & 255) << 16) | (ql[3] << 24);
    sl.y = (ql[4] & 255) | ((ql[5] & 255) << 8) | ((ql[6] & 255) << 16) | (ql[7] << 24);
    *(uint2*)(g_Xhi + i) = sh;
    *(uint2*)(g_Xlo + i) = sl;
}

// ---------------- GEMM ----------------
// one stage load: B tile 128x64 (W), A_hi 128x64, A_lo 128x64, all int8
__device__ __forceinline__ void load_stage(uint32_t slot, int bm0, int bn0,
                                           int kc, int tid) {
    int row = tid >> 2, c = tid & 3;
    uint32_t soff = (uint32_t)(row * ROW_PITCH + c * 16);
    size_t koff = (size_t)kc * BK + c * 16;
    cp_async16(slot + B_OFF + soff, g_W8 + (size_t)(bn0 + row) * IN_F + koff);
    cp_async16(slot + AH_OFF + soff, g_Xhi + (size_t)(bm0 + row) * IN_F + koff);
    cp_async16(slot + AL_OFF + soff, g_Xlo + (size_t)(bm0 + row) * IN_F + koff);
}

__global__ void __launch_bounds__(THREADS, 1)
gemm_kernel(const int* __restrict__ bias, const float* __restrict__ scale_p,
            float* __restrict__ out) {
    extern __shared__ char dsmem[];
    const uint32_t sb = smem_u32(dsmem);
    const int tid = threadIdx.x;

    // supertile rasterization: pm varies fastest within groups of 8 (W L2 reuse)
    const int n_m = N_TOKENS / BM;   // 64
    const int n_n = OUT_F / BN;      // 128
    const int GROUP = 8;
    int pid = blockIdx.x;
    int nig = GROUP * n_n;
    int gid = pid / nig;
    int fm = gid * GROUP;
    int gsz = (GROUP < n_m - fm) ? GROUP : (n_m - fm);
    int pm = fm + (pid % nig) % gsz;
    int pn = (pid % nig) / gsz;
    const int bm0 = pm * BM;
    const int bn0 = pn * BN;

    const int w = tid >> 5, lane = tid & 31;
    const int wm = w & 3, wn = w >> 2;          // 4x4 warp grid, 32x32 tiles
    const int g = lane >> 2, tg = lane & 3;

    // accumulators: [plane][mt][nt][4]
    int acc[2][2][4][4];
#pragma unroll
    for (int p = 0; p < 2; p++)
#pragma unroll
        for (int mt = 0; mt < 2; mt++)
#pragma unroll
            for (int nt = 0; nt < 4; nt++)
#pragma unroll
                for (int r = 0; r < 4; r++) acc[p][mt][nt][r] = 0;

    // prologue: fill stages 0..2
#pragma unroll
    for (int i = 0; i < NSTAGE - 1; i++) {
        load_stage(sb + i * STAGE_BYTES, bm0, bn0, i, tid);
        asm volatile("cp.async.commit_group;" ::: "memory");
    }

    // per-thread fragment base addresses (relative to stage)
    const uint32_t aBase = (uint32_t)((wm * 32 + g) * ROW_PITCH + tg * 4);
    const uint32_t bBase = (uint32_t)((wn * 32 + g) * ROW_PITCH + tg * 4);

    for (int kc = 0; kc < NKC; kc++) {
        asm volatile("cp.async.wait_group 2;" ::: "memory");
        __syncthreads();

        int kn = kc + (NSTAGE - 1);
        if (kn < NKC)
            load_stage(sb + (kn & (NSTAGE - 1)) * STAGE_BYTES, bm0, bn0, kn, tid);
        asm volatile("cp.async.commit_group;" ::: "memory");

        const uint32_t stg = sb + (kc & (NSTAGE - 1)) * STAGE_BYTES;
        const uint32_t aS = stg + AH_OFF + aBase;   // hi plane; lo = +10240
        const uint32_t bS = stg + B_OFF + bBase;

#pragma unroll
        for (int ks = 0; ks < 2; ks++) {
            const uint32_t k0 = ks * 32;
            int af[2][2][4];  // [plane][mt][reg]
#pragma unroll
            for (int p = 0; p < 2; p++) {
                uint32_t pa = aS + p * (AL_OFF - AH_OFF) + k0;
#pragma unroll
                for (int mt = 0; mt < 2; mt++) {
                    uint32_t ma = pa + mt * (16 * ROW_PITCH);
                    af[p][mt][0] = lds32(ma);
                    af[p][mt][1] = lds32(ma + 8 * ROW_PITCH);
                    af[p][mt][2] = lds32(ma + 16);
                    af[p][mt][3] = lds32(ma + 8 * ROW_PITCH + 16);
                }
            }
#pragma unroll
            for (int nt = 0; nt < 4; nt++) {
                uint32_t na = bS + nt * (8 * ROW_PITCH) + k0;
                int b0 = lds32(na);
                int b1 = lds32(na + 16);
#pragma unroll
                for (int p = 0; p < 2; p++)
#pragma unroll
                    for (int mt = 0; mt < 2; mt++)
                        mma_s8(acc[p][mt][nt],
                               af[p][mt][0], af[p][mt][1], af[p][mt][2], af[p][mt][3],
                               b0, b1);
            }
        }
    }

    // ---------------- epilogue ----------------
    float ws = __ldg(scale_p);
#pragma unroll
    for (int mt = 0; mt < 2; mt++) {
        int r0 = bm0 + wm * 32 + mt * 16 + g;
#pragma unroll
        for (int nt = 0; nt < 4; nt++) {
            int col = bn0 + wn * 32 + nt * 8 + tg * 2;
            int2 bv = *(const int2*)(bias + col);
            float b0f = ws * (float)bv.x;
            float b1f = ws * (float)bv.y;
            const int* hi = acc[0][mt][nt];
            const int* lo = acc[1][mt][nt];
            float2 v;
            v.x = ws * (S0 * (float)hi[0] + S1 * (float)lo[0]) + b0f;
            v.y = ws * (S0 * (float)hi[1] + S1 * (float)lo[1]) + b1f;
            *(float2*)(out + (size_t)r0 * OUT_F + col) = v;
            v.x = ws * (S0 * (float)hi[2] + S1 * (float)lo[2]) + b0f;
            v.y = ws * (S0 * (float)hi[3] + S1 * (float)lo[3]) + b1f;
            *(float2*)(out + (size_t)(r0 + 8) * OUT_F + col) = v;
        }
    }
}

// ---------------- launch ----------------
extern "C" void kernel_launch(void* const* d_in, const int* in_sizes, int n_in,
                              void* d_out, int out_size) {
    const float* x     = (const float*)d_in[0];
    const int*   wgt   = (const int*)d_in[1];
    const int*   bias  = (const int*)d_in[2];
    const float* scale = (const float*)d_in[3];
    float* out = (float*)d_out;

    convert_w_kernel<<<16384, 256>>>(wgt);   // 67.1M elems, 16/thread
    convert_x_kernel<<<16384, 256>>>(x);     // 33.5M elems, 8/thread

    cudaFuncSetAttribute(gemm_kernel, cudaFuncAttributeMaxDynamicSharedMemorySize,
                         SMEM_BYTES);
    gemm_kernel<<<(N_TOKENS / BM) * (OUT_F / BN), THREADS, SMEM_BYTES>>>(bias, scale, out);
}

// round 3
// speedup vs baseline: 1.0341x; 1.0341x over previous
#include <cuda_runtime.h>
#include <cstdint>

#define N_TOKENS 8192
#define IN_F     4096
#define OUT_F    16384

#define BM 128
#define BN 128
#define BK 64              // int8 elems per k-chunk
#define NKC (IN_F / BK)    // 64
#define NSTAGE 4
#define THREADS 512

// smem stage layout: rows padded 64B -> 80B (conflict-free LDSM row pointers)
#define ROW_PITCH 80
#define B_OFF   0
#define AH_OFF  (128 * ROW_PITCH)          // 10240
#define AL_OFF  (2 * 128 * ROW_PITCH)      // 20480
#define STAGE_BYTES (3 * 128 * ROW_PITCH)  // 30720
#define SMEM_BYTES  (NSTAGE * STAGE_BYTES) // 122880

// quantization constants: x ~= S0*q_hi + S1*q_lo
#define S0 0.0625f
#define S1 (0.0625f / 252.0f)

// -------- static scratch (no runtime allocation allowed) --------
__device__ int8_t g_W8 [(size_t)OUT_F * IN_F];     // 64 MB
__device__ int8_t g_Xhi[(size_t)N_TOKENS * IN_F];  // 32 MB
__device__ int8_t g_Xlo[(size_t)N_TOKENS * IN_F];  // 32 MB

// ---------------- helpers ----------------
__device__ __forceinline__ uint32_t smem_u32(const void* p) {
    uint32_t a;
    asm("{ .reg .u64 t; cvta.to.shared.u64 t, %1; cvt.u32.u64 %0, t; }" : "=r"(a) : "l"(p));
    return a;
}

__device__ __forceinline__ void cp_async16(uint32_t dst, const void* src) {
    asm volatile("cp.async.cg.shared.global [%0], [%1], 16;" :: "r"(dst), "l"(src));
}

__device__ __forceinline__ void ldsm_x4(int* r, uint32_t a) {
    asm volatile("ldmatrix.sync.aligned.m8n8.x4.shared.b16 {%0,%1,%2,%3}, [%4];"
                 : "=r"(r[0]), "=r"(r[1]), "=r"(r[2]), "=r"(r[3]) : "r"(a));
}

__device__ __forceinline__ void mma_s8(int* c, const int* a, int b0, int b1) {
    asm volatile(
        "mma.sync.aligned.m16n8k32.row.col.s32.s8.s8.s32 "
        "{%0,%1,%2,%3}, {%4,%5,%6,%7}, {%8,%9}, {%0,%1,%2,%3};"
        : "+r"(c[0]), "+r"(c[1]), "+r"(c[2]), "+r"(c[3])
        : "r"(a[0]), "r"(a[1]), "r"(a[2]), "r"(a[3]), "r"(b0), "r"(b1));
}

// ---------------- conversion kernels ----------------
__global__ void convert_w_kernel(const int* __restrict__ w) {
    size_t i = ((size_t)blockIdx.x * blockDim.x + threadIdx.x) * 16;
    const int4* p = (const int4*)(w + i);
    int4 a = p[0], b = p[1], c = p[2], d = p[3];
    uint4 st;
    st.x = (a.x & 255) | ((a.y & 255) << 8) | ((a.z & 255) << 16) | (a.w << 24);
    st.y = (b.x & 255) | ((b.y & 255) << 8) | ((b.z & 255) << 16) | (b.w << 24);
    st.z = (c.x & 255) | ((c.y & 255) << 8) | ((c.z & 255) << 16) | (c.w << 24);
    st.w = (d.x & 255) | ((d.y & 255) << 8) | ((d.z & 255) << 16) | (d.w << 24);
    *(uint4*)(g_W8 + i) = st;
}

__global__ void convert_x_kernel(const float* __restrict__ x) {
    size_t i = ((size_t)blockIdx.x * blockDim.x + threadIdx.x) * 8;
    float4 v0 = *(const float4*)(x + i);
    float4 v1 = *(const float4*)(x + i + 4);
    float vv[8] = {v0.x, v0.y, v0.z, v0.w, v1.x, v1.y, v1.z, v1.w};
    int qh[8], ql[8];
#pragma unroll
    for (int u = 0; u < 8; u++) {
        float h = rintf(vv[u] * 16.0f);              // x / S0
        h = fminf(fmaxf(h, -127.0f), 127.0f);
        float r = vv[u] - h * S0;
        float l = rintf(r * (16.0f * 252.0f));       // r / S1
        l = fminf(fmaxf(l, -127.0f), 127.0f);
        qh[u] = (int)h;
        ql[u] = (int)l;
    }
    uint2 sh, sl;
    sh.x = (qh[0] & 255) | ((qh[1] & 255) << 8) | ((qh[2] & 255) << 16) | (qh[3] << 24);
    sh.y = (qh[4] & 255) | ((qh[5] & 255) << 8) | ((qh[6] & 255) << 16) | (qh[7] << 24);
    sl.x = (ql[0] & 255) | ((ql[1] & 255) << 8) | ((ql[2] & 255) << 16) | (ql[3] << 24);
    sl.y = (ql[4] & 255) | ((ql[5] & 255) << 8) | ((ql[6] & 255) << 16) | (ql[7] << 24);
    *(uint2*)(g_Xhi + i) = sh;
    *(uint2*)(g_Xlo + i) = sl;
}

// ---------------- GEMM ----------------
// one stage load: B tile 128x64 (W), A_hi 128x64, A_lo 128x64, all int8
__device__ __forceinline__ void load_stage(uint32_t slot, int bm0, int bn0,
                                           int kc, int tid) {
    int row = tid >> 2, c = tid & 3;
    uint32_t soff = (uint32_t)(row * ROW_PITCH + c * 16);
    size_t koff = (size_t)kc * BK + c * 16;
    cp_async16(slot + B_OFF + soff, g_W8 + (size_t)(bn0 + row) * IN_F + koff);
    cp_async16(slot + AH_OFF + soff, g_Xhi + (size_t)(bm0 + row) * IN_F + koff);
    cp_async16(slot + AL_OFF + soff, g_Xlo + (size_t)(bm0 + row) * IN_F + koff);
}

__global__ void __launch_bounds__(THREADS, 1)
gemm_kernel(const int* __restrict__ bias, const float* __restrict__ scale_p,
            float* __restrict__ out) {
    extern __shared__ char dsmem[];
    const uint32_t sb = smem_u32(dsmem);
    const int tid = threadIdx.x;

    // supertile rasterization: pm varies fastest within groups of 8 (W L2 reuse)
    const int n_m = N_TOKENS / BM;   // 64
    const int n_n = OUT_F / BN;      // 128
    const int GROUP = 8;
    int pid = blockIdx.x;
    int nig = GROUP * n_n;
    int gid = pid / nig;
    int fm = gid * GROUP;
    int gsz = (GROUP < n_m - fm) ? GROUP : (n_m - fm);
    int pm = fm + (pid % nig) % gsz;
    int pn = (pid % nig) / gsz;
    const int bm0 = pm * BM;
    const int bn0 = pn * BN;

    const int w = tid >> 5, lane = tid & 31;
    const int wm = w & 3, wn = w >> 2;          // 4x4 warp grid, 32x32 tiles
    const int g = lane >> 2, tg = lane & 3;

    // ldmatrix per-lane row-pointer offsets
    const int j = lane & 7, m = lane >> 3;
    // A: matrices {rows0-7/b0-15, rows8-15/b0-15, rows0-7/b16-31, rows8-15/b16-31}
    const uint32_t aLdsm = (uint32_t)((wm * 32 + j + (m & 1) * 8) * ROW_PITCH + (m >> 1) * 16);
    // B: matrices {nt rows0-7/b0-15, nt b16-31, nt+1 b0-15, nt+1 b16-31}
    const uint32_t bLdsm = (uint32_t)((wn * 32 + j + (m >> 1) * 8) * ROW_PITCH + (m & 1) * 16);

    // accumulators: [plane][mt][nt][4]
    int acc[2][2][4][4];
#pragma unroll
    for (int p = 0; p < 2; p++)
#pragma unroll
        for (int mt = 0; mt < 2; mt++)
#pragma unroll
            for (int nt = 0; nt < 4; nt++)
#pragma unroll
                for (int r = 0; r < 4; r++) acc[p][mt][nt][r] = 0;

    // prologue: fill stages 0..2
#pragma unroll
    for (int i = 0; i < NSTAGE - 1; i++) {
        load_stage(sb + i * STAGE_BYTES, bm0, bn0, i, tid);
        asm volatile("cp.async.commit_group;" ::: "memory");
    }

    for (int kc = 0; kc < NKC; kc++) {
        asm volatile("cp.async.wait_group 2;" ::: "memory");
        __syncthreads();

        int kn = kc + (NSTAGE - 1);
        if (kn < NKC)
            load_stage(sb + (kn & (NSTAGE - 1)) * STAGE_BYTES, bm0, bn0, kn, tid);
        asm volatile("cp.async.commit_group;" ::: "memory");

        const uint32_t stg = sb + (kc & (NSTAGE - 1)) * STAGE_BYTES;

#pragma unroll
        for (int ks = 0; ks < 2; ks++) {
            const uint32_t k0 = ks * 32;
            // A fragments: one ldmatrix.x4 per (plane, mt) = full m16n8k32 A operand
            int af[2][2][4];
#pragma unroll
            for (int p = 0; p < 2; p++) {
                uint32_t pa = stg + (p ? AL_OFF : AH_OFF) + aLdsm + k0;
                ldsm_x4(af[p][0], pa);
                ldsm_x4(af[p][1], pa + 16 * ROW_PITCH);
            }
            // B fragments: one ldmatrix.x4 per nt-pair (r0,r1 = nt; r2,r3 = nt+1)
            int bf[2][4];
            {
                uint32_t ba = stg + B_OFF + bLdsm + k0;
                ldsm_x4(bf[0], ba);
                ldsm_x4(bf[1], ba + 16 * ROW_PITCH);
            }
#pragma unroll
            for (int nt = 0; nt < 4; nt++) {
                int b0 = bf[nt >> 1][(nt & 1) * 2];
                int b1 = bf[nt >> 1][(nt & 1) * 2 + 1];
#pragma unroll
                for (int p = 0; p < 2; p++)
#pragma unroll
                    for (int mt = 0; mt < 2; mt++)
                        mma_s8(acc[p][mt][nt], af[p][mt], b0, b1);
            }
        }
    }

    // ---------------- epilogue ----------------
    float ws = __ldg(scale_p);
#pragma unroll
    for (int mt = 0; mt < 2; mt++) {
        int r0 = bm0 + wm * 32 + mt * 16 + g;
#pragma unroll
        for (int nt = 0; nt < 4; nt++) {
            int col = bn0 + wn * 32 + nt * 8 + tg * 2;
            int2 bv = *(const int2*)(bias + col);
            float b0f = ws * (float)bv.x;
            float b1f = ws * (float)bv.y;
            const int* hi = acc[0][mt][nt];
            const int* lo = acc[1][mt][nt];
            float2 v;
            v.x = ws * (S0 * (float)hi[0] + S1 * (float)lo[0]) + b0f;
            v.y = ws * (S0 * (float)hi[1] + S1 * (float)lo[1]) + b1f;
            *(float2*)(out + (size_t)r0 * OUT_F + col) = v;
            v.x = ws * (S0 * (float)hi[2] + S1 * (float)lo[2]) + b0f;
            v.y = ws * (S0 * (float)hi[3] + S1 * (float)lo[3]) + b1f;
            *(float2*)(out + (size_t)(r0 + 8) * OUT_F + col) = v;
        }
    }
}

// ---------------- launch ----------------
extern "C" void kernel_launch(void* const* d_in, const int* in_sizes, int n_in,
                              void* d_out, int out_size) {
    const float* x     = (const float*)d_in[0];
    const int*   wgt   = (const int*)d_in[1];
    const int*   bias  = (const int*)d_in[2];
    const float* scale = (const float*)d_in[3];
    float* out = (float*)d_out;

    convert_w_kernel<<<16384, 256>>>(wgt);   // 67.1M elems, 16/thread
    convert_x_kernel<<<16384, 256>>>(x);     // 33.5M elems, 8/thread

    cudaFuncSetAttribute(gemm_kernel, cudaFuncAttributeMaxDynamicSharedMemorySize,
                         SMEM_BYTES);
    gemm_kernel<<<(N_TOKENS / BM) * (OUT_F / BN), THREADS, SMEM_BYTES>>>(bias, scale, out);
}

// round 4
// speedup vs baseline: 5.0404x; 4.8744x over previous
#include <cuda_runtime.h>
#include <cuda_fp16.h>
#include <cstdint>

#define N_TOKENS 8192
#define IN_F     4096
#define OUT_F    16384

#define BM 128
#define BN 256
#define BK 64              // fp16 elems per k-chunk = 128B of payload per row
#define NKC (IN_F / BK)    // 64
#define NSTAGE 3
#define THREADS 512

// smem rows padded 128B -> 144B (LDSM row ptrs land on banks 4r%32: conflict-free)
#define ROW_PITCH 144
#define A_OFF   0
#define B_OFF   (BM * ROW_PITCH)                       // 18432
#define STAGE_BYTES ((BM + BN) * ROW_PITCH)            // 55296
#define SMEM_BYTES  (NSTAGE * STAGE_BYTES)             // 165888

// -------- static scratch (no runtime allocation allowed) --------
__device__ __half g_Wh[(size_t)OUT_F * IN_F];     // 128 MB
__device__ __half g_Xh[(size_t)N_TOKENS * IN_F];  // 64 MB

// ---------------- helpers ----------------
__device__ __forceinline__ uint32_t smem_u32(const void* p) {
    uint32_t a;
    asm("{ .reg .u64 t; cvta.to.shared.u64 t, %1; cvt.u32.u64 %0, t; }" : "=r"(a) : "l"(p));
    return a;
}

__device__ __forceinline__ void cp_async16(uint32_t dst, const void* src) {
    asm volatile("cp.async.cg.shared.global [%0], [%1], 16;" :: "r"(dst), "l"(src));
}

__device__ __forceinline__ void ldsm_x4(uint32_t* r, uint32_t a) {
    asm volatile("ldmatrix.sync.aligned.m8n8.x4.shared.b16 {%0,%1,%2,%3}, [%4];"
                 : "=r"(r[0]), "=r"(r[1]), "=r"(r[2]), "=r"(r[3]) : "r"(a));
}

// m16n8k16 fp16 MMA, fp32 accumulate
__device__ __forceinline__ void mma_f16(float* c, const uint32_t* a, uint32_t b0, uint32_t b1) {
    asm volatile(
        "mma.sync.aligned.m16n8k16.row.col.f32.f16.f16.f32 "
        "{%0,%1,%2,%3}, {%4,%5,%6,%7}, {%8,%9}, {%0,%1,%2,%3};"
        : "+f"(c[0]), "+f"(c[1]), "+f"(c[2]), "+f"(c[3])
        : "r"(a[0]), "r"(a[1]), "r"(a[2]), "r"(a[3]), "r"(b0), "r"(b1));
}

// ---------------- conversion kernels ----------------
__global__ void convert_w_kernel(const int* __restrict__ w) {
    size_t i = ((size_t)blockIdx.x * blockDim.x + threadIdx.x) * 8;
    int4 a = *(const int4*)(w + i);
    int4 b = *(const int4*)(w + i + 4);
    __half2 h0 = __floats2half2_rn((float)a.x, (float)a.y);
    __half2 h1 = __floats2half2_rn((float)a.z, (float)a.w);
    __half2 h2 = __floats2half2_rn((float)b.x, (float)b.y);
    __half2 h3 = __floats2half2_rn((float)b.z, (float)b.w);
    uint4 st;
    st.x = *(unsigned*)&h0; st.y = *(unsigned*)&h1;
    st.z = *(unsigned*)&h2; st.w = *(unsigned*)&h3;
    *(uint4*)(g_Wh + i) = st;
}

__global__ void convert_x_kernel(const float* __restrict__ x) {
    size_t i = ((size_t)blockIdx.x * blockDim.x + threadIdx.x) * 8;
    float4 v0 = *(const float4*)(x + i);
    float4 v1 = *(const float4*)(x + i + 4);
    __half2 h0 = __floats2half2_rn(v0.x, v0.y);
    __half2 h1 = __floats2half2_rn(v0.z, v0.w);
    __half2 h2 = __floats2half2_rn(v1.x, v1.y);
    __half2 h3 = __floats2half2_rn(v1.z, v1.w);
    uint4 st;
    st.x = *(unsigned*)&h0; st.y = *(unsigned*)&h1;
    st.z = *(unsigned*)&h2; st.w = *(unsigned*)&h3;
    *(uint4*)(g_Xh + i) = st;
}

// ---------------- GEMM ----------------
// one stage: A (x) 128 rows x 128B, B (W) 256 rows x 128B
__device__ __forceinline__ void load_stage(uint32_t slot, int bm0, int bn0,
                                           int kc, int tid) {
    // A: 1024 16B-chunks
#pragma unroll
    for (int i = 0; i < 2; i++) {
        int ch = i * 512 + tid;
        int row = ch >> 3, c = ch & 7;
        cp_async16(slot + A_OFF + (uint32_t)(row * ROW_PITCH + c * 16),
                   g_Xh + (size_t)(bm0 + row) * IN_F + (size_t)kc * BK + c * 8);
    }
    // B: 2048 16B-chunks
#pragma unroll
    for (int i = 0; i < 4; i++) {
        int ch = i * 512 + tid;
        int row = ch >> 3, c = ch & 7;
        cp_async16(slot + B_OFF + (uint32_t)(row * ROW_PITCH + c * 16),
                   g_Wh + (size_t)(bn0 + row) * IN_F + (size_t)kc * BK + c * 8);
    }
}

__global__ void __launch_bounds__(THREADS, 1)
gemm_kernel(const int* __restrict__ bias, const float* __restrict__ scale_p,
            float* __restrict__ out) {
    extern __shared__ char dsmem[];
    const uint32_t sb = smem_u32(dsmem);
    const int tid = threadIdx.x;

    // supertile rasterization: pm varies fastest in groups of 8 (W L2 reuse)
    const int n_m = N_TOKENS / BM;   // 64
    const int n_n = OUT_F / BN;      // 64
    const int GROUP = 8;
    int pid = blockIdx.x;
    int nig = GROUP * n_n;
    int gid = pid / nig;
    int fm = gid * GROUP;
    int gsz = (GROUP < n_m - fm) ? GROUP : (n_m - fm);
    int pm = fm + (pid % nig) % gsz;
    int pn = (pid % nig) / gsz;
    const int bm0 = pm * BM;
    const int bn0 = pn * BN;

    const int w = tid >> 5, lane = tid & 31;
    const int wm = w & 3, wn = w >> 2;          // 4x4 warp grid, 32x64 tiles
    const int g = lane >> 2, tg = lane & 3;
    const int j = lane & 7, m8 = lane >> 3;

    // ldmatrix lane->row-pointer offsets
    // A x4: matrices {m0-7/k0-7, m8-15/k0-7, m0-7/k8-15, m8-15/k8-15}
    const uint32_t aLdsm =
        (uint32_t)((wm * 32 + j + (m8 & 1) * 8) * ROW_PITCH + (m8 >> 1) * 16);
    // B x4: matrices {nt/k0-7, nt/k8-15, nt+1/k0-7, nt+1/k8-15}
    const uint32_t bLdsm =
        (uint32_t)((wn * 64 + (m8 >> 1) * 8 + j) * ROW_PITCH + (m8 & 1) * 16);

    float acc[2][8][4];
#pragma unroll
    for (int mt = 0; mt < 2; mt++)
#pragma unroll
        for (int nt = 0; nt < 8; nt++)
#pragma unroll
            for (int r = 0; r < 4; r++) acc[mt][nt][r] = 0.f;

    // prologue: stages 0,1
#pragma unroll
    for (int i = 0; i < NSTAGE - 1; i++) {
        load_stage(sb + i * STAGE_BYTES, bm0, bn0, i, tid);
        asm volatile("cp.async.commit_group;" ::: "memory");
    }

    int slot = 0;
    for (int kc = 0; kc < NKC; kc++) {
        asm volatile("cp.async.wait_group 1;" ::: "memory");
        __syncthreads();

        int kn = kc + (NSTAGE - 1);
        int ls = slot + (NSTAGE - 1); if (ls >= NSTAGE) ls -= NSTAGE;
        if (kn < NKC)
            load_stage(sb + ls * STAGE_BYTES, bm0, bn0, kn, tid);
        asm volatile("cp.async.commit_group;" ::: "memory");

        const uint32_t stg = sb + slot * STAGE_BYTES;
        if (++slot == NSTAGE) slot = 0;

#pragma unroll
        for (int ks = 0; ks < 4; ks++) {         // 4 x k16
            const uint32_t k0 = ks * 32;         // bytes
            uint32_t af[2][4];
            ldsm_x4(af[0], stg + A_OFF + aLdsm + k0);
            ldsm_x4(af[1], stg + A_OFF + aLdsm + k0 + 16 * ROW_PITCH);
            uint32_t bf[4][4];                   // [nt-pair][reg]
#pragma unroll
            for (int bp = 0; bp < 4; bp++)
                ldsm_x4(bf[bp], stg + B_OFF + bLdsm + k0 + bp * (16 * ROW_PITCH));
#pragma unroll
            for (int nt = 0; nt < 8; nt++) {
                uint32_t b0 = bf[nt >> 1][(nt & 1) * 2];
                uint32_t b1 = bf[nt >> 1][(nt & 1) * 2 + 1];
#pragma unroll
                for (int mt = 0; mt < 2; mt++)
                    mma_f16(acc[mt][nt], af[mt], b0, b1);
            }
        }
    }

    // ---------------- epilogue ----------------
    float ws = __ldg(scale_p);
#pragma unroll
    for (int mt = 0; mt < 2; mt++) {
        int r0 = bm0 + wm * 32 + mt * 16 + g;
#pragma unroll
        for (int nt = 0; nt < 8; nt++) {
            int col = bn0 + wn * 64 + nt * 8 + tg * 2;
            int2 bv = *(const int2*)(bias + col);
            float b0f = ws * (float)bv.x;
            float b1f = ws * (float)bv.y;
            const float* a = acc[mt][nt];
            float2 v;
            v.x = ws * a[0] + b0f;
            v.y = ws * a[1] + b1f;
            *(float2*)(out + (size_t)r0 * OUT_F + col) = v;
            v.x = ws * a[2] + b0f;
            v.y = ws * a[3] + b1f;
            *(float2*)(out + (size_t)(r0 + 8) * OUT_F + col) = v;
        }
    }
}

// ---------------- launch ----------------
extern "C" void kernel_launch(void* const* d_in, const int* in_sizes, int n_in,
                              void* d_out, int out_size) {
    const float* x     = (const float*)d_in[0];
    const int*   wgt   = (const int*)d_in[1];
    const int*   bias  = (const int*)d_in[2];
    const float* scale = (const float*)d_in[3];
    float* out = (float*)d_out;

    convert_w_kernel<<<32768, 256>>>(wgt);   // 67.1M elems, 8/thread
    convert_x_kernel<<<16384, 256>>>(x);     // 33.5M elems, 8/thread

    cudaFuncSetAttribute(gemm_kernel, cudaFuncAttributeMaxDynamicSharedMemorySize,
                         SMEM_BYTES);
    gemm_kernel<<<(N_TOKENS / BM) * (OUT_F / BN), THREADS, SMEM_BYTES>>>(bias, scale, out);
}

// round 5
// speedup vs baseline: 5.1102x; 1.0138x over previous
#include <cuda_runtime.h>
#include <cuda_fp16.h>
#include <cstdint>

#define N_TOKENS 8192
#define IN_F     4096
#define OUT_F    16384

#define BM 128
#define BN 256
#define BK 128             // fp16 elems per k-chunk = 256B payload per row
#define NKC (IN_F / BK)    // 32
#define NSTAGE 2
#define THREADS 512

// smem rows padded 256B -> 272B (LDSM row ptrs on banks 4r%32: conflict-free)
#define ROW_PITCH 272
#define A_OFF   0
#define B_OFF   (BM * ROW_PITCH)                       // 34816
#define STAGE_BYTES ((BM + BN) * ROW_PITCH)            // 104448
#define SMEM_BYTES  (NSTAGE * STAGE_BYTES)             // 208896

// -------- static scratch (no runtime allocation allowed) --------
__device__ __half g_Wh[(size_t)OUT_F * IN_F];     // 128 MB
__device__ __half g_Xh[(size_t)N_TOKENS * IN_F];  // 64 MB

// ---------------- helpers ----------------
__device__ __forceinline__ uint32_t smem_u32(const void* p) {
    uint32_t a;
    asm("{ .reg .u64 t; cvta.to.shared.u64 t, %1; cvt.u32.u64 %0, t; }" : "=r"(a) : "l"(p));
    return a;
}

__device__ __forceinline__ void cp_async16(uint32_t dst, const void* src) {
    asm volatile("cp.async.cg.shared.global [%0], [%1], 16;" :: "r"(dst), "l"(src));
}

__device__ __forceinline__ void ldsm_x4(uint32_t* r, uint32_t a) {
    asm volatile("ldmatrix.sync.aligned.m8n8.x4.shared.b16 {%0,%1,%2,%3}, [%4];"
                 : "=r"(r[0]), "=r"(r[1]), "=r"(r[2]), "=r"(r[3]) : "r"(a));
}

// m16n8k16 fp16 MMA, fp32 accumulate
__device__ __forceinline__ void mma_f16(float* c, const uint32_t* a, uint32_t b0, uint32_t b1) {
    asm volatile(
        "mma.sync.aligned.m16n8k16.row.col.f32.f16.f16.f32 "
        "{%0,%1,%2,%3}, {%4,%5,%6,%7}, {%8,%9}, {%0,%1,%2,%3};"
        : "+f"(c[0]), "+f"(c[1]), "+f"(c[2]), "+f"(c[3])
        : "r"(a[0]), "r"(a[1]), "r"(a[2]), "r"(a[3]), "r"(b0), "r"(b1));
}

// ---------------- conversion kernels ----------------
__global__ void convert_w_kernel(const int* __restrict__ w) {
    size_t i = ((size_t)blockIdx.x * blockDim.x + threadIdx.x) * 8;
    int4 a = *(const int4*)(w + i);
    int4 b = *(const int4*)(w + i + 4);
    __half2 h0 = __floats2half2_rn((float)a.x, (float)a.y);
    __half2 h1 = __floats2half2_rn((float)a.z, (float)a.w);
    __half2 h2 = __floats2half2_rn((float)b.x, (float)b.y);
    __half2 h3 = __floats2half2_rn((float)b.z, (float)b.w);
    uint4 st;
    st.x = *(unsigned*)&h0; st.y = *(unsigned*)&h1;
    st.z = *(unsigned*)&h2; st.w = *(unsigned*)&h3;
    *(uint4*)(g_Wh + i) = st;
}

__global__ void convert_x_kernel(const float* __restrict__ x) {
    size_t i = ((size_t)blockIdx.x * blockDim.x + threadIdx.x) * 8;
    float4 v0 = *(const float4*)(x + i);
    float4 v1 = *(const float4*)(x + i + 4);
    __half2 h0 = __floats2half2_rn(v0.x, v0.y);
    __half2 h1 = __floats2half2_rn(v0.z, v0.w);
    __half2 h2 = __floats2half2_rn(v1.x, v1.y);
    __half2 h3 = __floats2half2_rn(v1.z, v1.w);
    uint4 st;
    st.x = *(unsigned*)&h0; st.y = *(unsigned*)&h1;
    st.z = *(unsigned*)&h2; st.w = *(unsigned*)&h3;
    *(uint4*)(g_Xh + i) = st;
}

// ---------------- GEMM ----------------
// one stage: A (x) 128 rows x 256B, B (W) 256 rows x 256B
__device__ __forceinline__ void load_stage(uint32_t slot, int bm0, int bn0,
                                           int kc, int tid) {
    // A: 2048 16B-chunks (4 per thread)
#pragma unroll
    for (int i = 0; i < 4; i++) {
        int ch = i * 512 + tid;
        int row = ch >> 4, c = ch & 15;
        cp_async16(slot + A_OFF + (uint32_t)(row * ROW_PITCH + c * 16),
                   g_Xh + (size_t)(bm0 + row) * IN_F + (size_t)kc * BK + c * 8);
    }
    // B: 4096 16B-chunks (8 per thread)
#pragma unroll
    for (int i = 0; i < 8; i++) {
        int ch = i * 512 + tid;
        int row = ch >> 4, c = ch & 15;
        cp_async16(slot + B_OFF + (uint32_t)(row * ROW_PITCH + c * 16),
                   g_Wh + (size_t)(bn0 + row) * IN_F + (size_t)kc * BK + c * 8);
    }
}

__global__ void __launch_bounds__(THREADS, 1)
gemm_kernel(const int* __restrict__ bias, const float* __restrict__ scale_p,
            float* __restrict__ out) {
    extern __shared__ char dsmem[];
    const uint32_t sb = smem_u32(dsmem);
    const int tid = threadIdx.x;

    // supertile rasterization: pm varies fastest in groups of 8 (W L2 reuse)
    const int n_m = N_TOKENS / BM;   // 64
    const int n_n = OUT_F / BN;      // 64
    const int GROUP = 8;
    int pid = blockIdx.x;
    int nig = GROUP * n_n;
    int gid = pid / nig;
    int fm = gid * GROUP;
    int gsz = (GROUP < n_m - fm) ? GROUP : (n_m - fm);
    int pm = fm + (pid % nig) % gsz;
    int pn = (pid % nig) / gsz;
    const int bm0 = pm * BM;
    const int bn0 = pn * BN;

    const int w = tid >> 5, lane = tid & 31;
    const int wm = w & 3, wn = w >> 2;          // 4x4 warp grid, 32x64 tiles
    const int g = lane >> 2, tg = lane & 3;
    const int j = lane & 7, m8 = lane >> 3;

    // ldmatrix lane->row-pointer offsets
    const uint32_t aLdsm =
        (uint32_t)((wm * 32 + j + (m8 & 1) * 8) * ROW_PITCH + (m8 >> 1) * 16);
    const uint32_t bLdsm =
        (uint32_t)((wn * 64 + (m8 >> 1) * 8 + j) * ROW_PITCH + (m8 & 1) * 16);

    float acc[2][8][4];
#pragma unroll
    for (int mt = 0; mt < 2; mt++)
#pragma unroll
        for (int nt = 0; nt < 8; nt++)
#pragma unroll
            for (int r = 0; r < 4; r++) acc[mt][nt][r] = 0.f;

    // prologue: stage 0
    load_stage(sb, bm0, bn0, 0, tid);
    asm volatile("cp.async.commit_group;" ::: "memory");

    for (int kc = 0; kc < NKC; kc++) {
        // all warps done computing kc-1 (slot (kc+1)&1 is reusable)
        __syncthreads();

        int kn = kc + 1;
        if (kn < NKC)
            load_stage(sb + (kn & 1) * STAGE_BYTES, bm0, bn0, kn, tid);
        asm volatile("cp.async.commit_group;" ::: "memory");

        // stage kc resident (kc+1 still in flight)
        asm volatile("cp.async.wait_group 1;" ::: "memory");
        __syncthreads();

        const uint32_t stg = sb + (kc & 1) * STAGE_BYTES;

#pragma unroll
        for (int ks = 0; ks < 8; ks++) {         // 8 x k16
            const uint32_t k0 = ks * 32;         // bytes
            uint32_t af[2][4];
            ldsm_x4(af[0], stg + A_OFF + aLdsm + k0);
            ldsm_x4(af[1], stg + A_OFF + aLdsm + k0 + 16 * ROW_PITCH);
            uint32_t bf[4][4];                   // [nt-pair][reg]
#pragma unroll
            for (int bp = 0; bp < 4; bp++)
                ldsm_x4(bf[bp], stg + B_OFF + bLdsm + k0 + bp * (16 * ROW_PITCH));
#pragma unroll
            for (int nt = 0; nt < 8; nt++) {
                uint32_t b0 = bf[nt >> 1][(nt & 1) * 2];
                uint32_t b1 = bf[nt >> 1][(nt & 1) * 2 + 1];
#pragma unroll
                for (int mt = 0; mt < 2; mt++)
                    mma_f16(acc[mt][nt], af[mt], b0, b1);
            }
        }
    }

    // ---------------- epilogue ----------------
    float ws = __ldg(scale_p);
#pragma unroll
    for (int mt = 0; mt < 2; mt++) {
        int r0 = bm0 + wm * 32 + mt * 16 + g;
#pragma unroll
        for (int nt = 0; nt < 8; nt++) {
            int col = bn0 + wn * 64 + nt * 8 + tg * 2;
            int2 bv = *(const int2*)(bias + col);
            float b0f = ws * (float)bv.x;
            float b1f = ws * (float)bv.y;
            const float* a = acc[mt][nt];
            float2 v;
            v.x = ws * a[0] + b0f;
            v.y = ws * a[1] + b1f;
            *(float2*)(out + (size_t)r0 * OUT_F + col) = v;
            v.x = ws * a[2] + b0f;
            v.y = ws * a[3] + b1f;
            *(float2*)(out + (size_t)(r0 + 8) * OUT_F + col) = v;
        }
    }
}

// ---------------- launch ----------------
extern "C" void kernel_launch(void* const* d_in, const int* in_sizes, int n_in,
                              void* d_out, int out_size) {
    const float* x     = (const float*)d_in[0];
    const int*   wgt   = (const int*)d_in[1];
    const int*   bias  = (const int*)d_in[2];
    const float* scale = (const float*)d_in[3];
    float* out = (float*)d_out;

    convert_w_kernel<<<32768, 256>>>(wgt);   // 67.1M elems, 8/thread
    convert_x_kernel<<<16384, 256>>>(x);     // 33.5M elems, 8/thread

    cudaFuncSetAttribute(gemm_kernel, cudaFuncAttributeMaxDynamicSharedMemorySize,
                         SMEM_BYTES);
    gemm_kernel<<<(N_TOKENS / BM) * (OUT_F / BN), THREADS, SMEM_BYTES>>>(bias, scale, out);
}

// round 6
// speedup vs baseline: 5.1651x; 1.0107x over previous
#include <cuda_runtime.h>
#include <cuda_fp16.h>
#include <cstdint>

#define N_TOKENS 8192
#define IN_F     4096
#define OUT_F    16384

#define BM 128
#define BN 256
#define BK 128             // fp16 elems per k-chunk = 256B payload per row
#define NKC (IN_F / BK)    // 32
#define NSTAGE 2
#define THREADS 256        // 8 warps, 2x4 grid of 64x64 warp tiles

// smem rows padded 256B -> 272B (LDSM row ptrs on banks 4r%32: conflict-free)
#define ROW_PITCH 272
#define A_OFF   0
#define B_OFF   (BM * ROW_PITCH)                       // 34816
#define STAGE_BYTES ((BM + BN) * ROW_PITCH)            // 104448
#define SMEM_BYTES  (NSTAGE * STAGE_BYTES)             // 208896

// -------- static scratch (no runtime allocation allowed) --------
__device__ __half g_Wh[(size_t)OUT_F * IN_F];     // 128 MB
__device__ __half g_Xh[(size_t)N_TOKENS * IN_F];  // 64 MB

// ---------------- helpers ----------------
__device__ __forceinline__ uint32_t smem_u32(const void* p) {
    uint32_t a;
    asm("{ .reg .u64 t; cvta.to.shared.u64 t, %1; cvt.u32.u64 %0, t; }" : "=r"(a) : "l"(p));
    return a;
}

__device__ __forceinline__ void cp_async16(uint32_t dst, const void* src) {
    asm volatile("cp.async.cg.shared.global [%0], [%1], 16;" :: "r"(dst), "l"(src));
}

__device__ __forceinline__ void ldsm_x4(uint32_t* r, uint32_t a) {
    asm volatile("ldmatrix.sync.aligned.m8n8.x4.shared.b16 {%0,%1,%2,%3}, [%4];"
                 : "=r"(r[0]), "=r"(r[1]), "=r"(r[2]), "=r"(r[3]) : "r"(a));
}

// m16n8k16 fp16 MMA, fp32 accumulate
__device__ __forceinline__ void mma_f16(float* c, const uint32_t* a, uint32_t b0, uint32_t b1) {
    asm volatile(
        "mma.sync.aligned.m16n8k16.row.col.f32.f16.f16.f32 "
        "{%0,%1,%2,%3}, {%4,%5,%6,%7}, {%8,%9}, {%0,%1,%2,%3};"
        : "+f"(c[0]), "+f"(c[1]), "+f"(c[2]), "+f"(c[3])
        : "r"(a[0]), "r"(a[1]), "r"(a[2]), "r"(a[3]), "r"(b0), "r"(b1));
}

// ---------------- conversion kernels ----------------
__global__ void convert_w_kernel(const int* __restrict__ w) {
    size_t i = ((size_t)blockIdx.x * blockDim.x + threadIdx.x) * 8;
    int4 a = *(const int4*)(w + i);
    int4 b = *(const int4*)(w + i + 4);
    __half2 h0 = __floats2half2_rn((float)a.x, (float)a.y);
    __half2 h1 = __floats2half2_rn((float)a.z, (float)a.w);
    __half2 h2 = __floats2half2_rn((float)b.x, (float)b.y);
    __half2 h3 = __floats2half2_rn((float)b.z, (float)b.w);
    uint4 st;
    st.x = *(unsigned*)&h0; st.y = *(unsigned*)&h1;
    st.z = *(unsigned*)&h2; st.w = *(unsigned*)&h3;
    *(uint4*)(g_Wh + i) = st;
}

__global__ void convert_x_kernel(const float* __restrict__ x) {
    size_t i = ((size_t)blockIdx.x * blockDim.x + threadIdx.x) * 8;
    float4 v0 = *(const float4*)(x + i);
    float4 v1 = *(const float4*)(x + i + 4);
    __half2 h0 = __floats2half2_rn(v0.x, v0.y);
    __half2 h1 = __floats2half2_rn(v0.z, v0.w);
    __half2 h2 = __floats2half2_rn(v1.x, v1.y);
    __half2 h3 = __floats2half2_rn(v1.z, v1.w);
    uint4 st;
    st.x = *(unsigned*)&h0; st.y = *(unsigned*)&h1;
    st.z = *(unsigned*)&h2; st.w = *(unsigned*)&h3;
    *(uint4*)(g_Xh + i) = st;
}

// ---------------- GEMM ----------------
// one stage: A (x) 128 rows x 256B, B (W) 256 rows x 256B
__device__ __forceinline__ void load_stage(uint32_t slot, int bm0, int bn0,
                                           int kc, int tid) {
    // A: 2048 16B-chunks (8 per thread)
#pragma unroll
    for (int i = 0; i < 8; i++) {
        int ch = i * 256 + tid;
        int row = ch >> 4, c = ch & 15;
        cp_async16(slot + A_OFF + (uint32_t)(row * ROW_PITCH + c * 16),
                   g_Xh + (size_t)(bm0 + row) * IN_F + (size_t)kc * BK + c * 8);
    }
    // B: 4096 16B-chunks (16 per thread)
#pragma unroll
    for (int i = 0; i < 16; i++) {
        int ch = i * 256 + tid;
        int row = ch >> 4, c = ch & 15;
        cp_async16(slot + B_OFF + (uint32_t)(row * ROW_PITCH + c * 16),
                   g_Wh + (size_t)(bn0 + row) * IN_F + (size_t)kc * BK + c * 8);
    }
}

__global__ void __launch_bounds__(THREADS, 1)
gemm_kernel(const int* __restrict__ bias, const float* __restrict__ scale_p,
            float* __restrict__ out) {
    extern __shared__ char dsmem[];
    const uint32_t sb = smem_u32(dsmem);
    const int tid = threadIdx.x;

    // supertile rasterization: pm varies fastest in groups of 8 (W L2 reuse)
    const int n_m = N_TOKENS / BM;   // 64
    const int n_n = OUT_F / BN;      // 64
    const int GROUP = 8;
    int pid = blockIdx.x;
    int nig = GROUP * n_n;
    int gid = pid / nig;
    int fm = gid * GROUP;
    int gsz = (GROUP < n_m - fm) ? GROUP : (n_m - fm);
    int pm = fm + (pid % nig) % gsz;
    int pn = (pid % nig) / gsz;
    const int bm0 = pm * BM;
    const int bn0 = pn * BN;

    const int w = tid >> 5, lane = tid & 31;
    const int wm = w & 1, wn = w >> 1;          // 2x4 warp grid, 64x64 tiles
    const int g = lane >> 2, tg = lane & 3;
    const int j = lane & 7, m8 = lane >> 3;

    // ldmatrix lane->row-pointer offsets
    // A x4 per mt: rows (wm*64 + mt*16 .. +15), k bytes 0..31
    const uint32_t aLdsm =
        (uint32_t)((wm * 64 + j + (m8 & 1) * 8) * ROW_PITCH + (m8 >> 1) * 16);
    // B x4 per nt-pair: rows (wn*64 + bp*16 .. +15)
    const uint32_t bLdsm =
        (uint32_t)((wn * 64 + (m8 >> 1) * 8 + j) * ROW_PITCH + (m8 & 1) * 16);

    float acc[4][8][4];
#pragma unroll
    for (int mt = 0; mt < 4; mt++)
#pragma unroll
        for (int nt = 0; nt < 8; nt++)
#pragma unroll
            for (int r = 0; r < 4; r++) acc[mt][nt][r] = 0.f;

    // prologue: stage 0
    load_stage(sb, bm0, bn0, 0, tid);
    asm volatile("cp.async.commit_group;" ::: "memory");

    for (int kc = 0; kc < NKC; kc++) {
        // all warps done computing kc-1 (slot (kc+1)&1 reusable)
        __syncthreads();

        int kn = kc + 1;
        if (kn < NKC)
            load_stage(sb + (kn & 1) * STAGE_BYTES, bm0, bn0, kn, tid);
        asm volatile("cp.async.commit_group;" ::: "memory");

        // stage kc resident (kc+1 still in flight)
        asm volatile("cp.async.wait_group 1;" ::: "memory");
        __syncthreads();

        const uint32_t stg = sb + (kc & 1) * STAGE_BYTES;

#pragma unroll
        for (int ks = 0; ks < 8; ks++) {         // 8 x k16
            const uint32_t k0 = ks * 32;         // bytes
            uint32_t af[4][4];
#pragma unroll
            for (int mt = 0; mt < 4; mt++)
                ldsm_x4(af[mt], stg + A_OFF + aLdsm + k0 + mt * (16 * ROW_PITCH));
            uint32_t bf[4][4];                   // [nt-pair][reg]
#pragma unroll
            for (int bp = 0; bp < 4; bp++)
                ldsm_x4(bf[bp], stg + B_OFF + bLdsm + k0 + bp * (16 * ROW_PITCH));
#pragma unroll
            for (int nt = 0; nt < 8; nt++) {
                uint32_t b0 = bf[nt >> 1][(nt & 1) * 2];
                uint32_t b1 = bf[nt >> 1][(nt & 1) * 2 + 1];
#pragma unroll
                for (int mt = 0; mt < 4; mt++)
                    mma_f16(acc[mt][nt], af[mt], b0, b1);
            }
        }
    }

    // ---------------- epilogue ----------------
    float ws = __ldg(scale_p);
#pragma unroll
    for (int mt = 0; mt < 4; mt++) {
        int r0 = bm0 + wm * 64 + mt * 16 + g;
#pragma unroll
        for (int nt = 0; nt < 8; nt++) {
            int col = bn0 + wn * 64 + nt * 8 + tg * 2;
            int2 bv = *(const int2*)(bias + col);
            float b0f = ws * (float)bv.x;
            float b1f = ws * (float)bv.y;
            const float* a = acc[mt][nt];
            float2 v;
            v.x = ws * a[0] + b0f;
            v.y = ws * a[1] + b1f;
            *(float2*)(out + (size_t)r0 * OUT_F + col) = v;
            v.x = ws * a[2] + b0f;
            v.y = ws * a[3] + b1f;
            *(float2*)(out + (size_t)(r0 + 8) * OUT_F + col) = v;
        }
    }
}

// ---------------- launch ----------------
extern "C" void kernel_launch(void* const* d_in, const int* in_sizes, int n_in,
                              void* d_out, int out_size) {
    const float* x     = (const float*)d_in[0];
    const int*   wgt   = (const int*)d_in[1];
    const int*   bias  = (const int*)d_in[2];
    const float* scale = (const float*)d_in[3];
    float* out = (float*)d_out;

    convert_w_kernel<<<32768, 256>>>(wgt);   // 67.1M elems, 8/thread
    convert_x_kernel<<<16384, 256>>>(x);     // 33.5M elems, 8/thread

    cudaFuncSetAttribute(gemm_kernel, cudaFuncAttributeMaxDynamicSharedMemorySize,
                         SMEM_BYTES);
    gemm_kernel<<<(N_TOKENS / BM) * (OUT_F / BN), THREADS, SMEM_BYTES>>>(bias, scale, out);
}